// round 9
// baseline (speedup 1.0000x reference)
#include <cuda_runtime.h>
#include <cstdint>

#define B_    32
#define IC_   16
#define OC_   16
#define KTOT  65536      // (M-1)*(N-1)
#define E_    131584     // edges
#define VOFF  65792      // M*(N-1)
#define KT    32         // k per tile
#define NBUF  4          // weight pipeline depth
#define NTILE (KTOT / KT)   // 2048

__device__ __forceinline__ unsigned long long pack2(float lo, float hi) {
    unsigned long long r;
    asm("mov.b64 %0, {%1, %2};" : "=l"(r) : "f"(lo), "f"(hi));
    return r;
}
__device__ __forceinline__ void fma2(unsigned long long &acc,
                                     unsigned long long a, unsigned long long b) {
    asm("fma.rn.f32x2 %0, %1, %2, %0;" : "+l"(acc) : "l"(a), "l"(b));
}
__device__ __forceinline__ float2 unpack2(unsigned long long v) {
    float2 f;
    asm("mov.b64 {%0, %1}, %2;" : "=f"(f.x), "=f"(f.y) : "l"(v));
    return f;
}
__device__ __forceinline__ void cp_async16(unsigned dst, const void* src) {
    asm volatile("cp.async.cg.shared.global [%0], [%1], 16;\n"
                 :: "r"(dst), "l"(src) : "memory");
}
__device__ __forceinline__ void cp_commit() {
    asm volatile("cp.async.commit_group;\n" ::: "memory");
}
template<int N>
__device__ __forceinline__ void cp_wait() {
    asm volatile("cp.async.wait_group %0;\n" :: "n"(N) : "memory");
}
__device__ __forceinline__ void bar_named(int id) {
    asm volatile("bar.sync %0, 256;" :: "r"(id) : "memory");
}

// Persistent CTAs: 148 blocks x 512 threads, each walks ~14 k-tiles.
// Per tile: 32 k-lanes x 16 warps (y = oh*8 + bg), all 32 batches, all 16 o.
// Slab rows 0..7 written by warps 0..7, read by warps 0..7 (oh=0); rows 8..15
// by warps 8..15 -> two independent named-barrier domains.
__global__ __launch_bounds__(512, 1)
void edges_kernel(const float* __restrict__ x,
                  const float4* __restrict__ w4,
                  const float* __restrict__ bias,
                  float* __restrict__ out)
{
    __shared__ float4 sw[NBUF][16 * KT];   // [buf][o*32 + klocal]

    const int lane = threadIdx.x;
    const int y    = threadIdx.y;
    const int oh   = y >> 3;
    const int bg   = y & 7;
    const int bbase = bg * 4;
    const int gstride = gridDim.x;

    // cooperative weight copy mapping (per-thread slot)
    const int tld = y * 32 + lane;
    const float4* wbase = w4 + (size_t)((tld >> 5) * IC_) * KTOT + (tld & 31);
    unsigned swdst[NBUF];
    #pragma unroll
    for (int s = 0; s < NBUF; ++s)
        swdst[s] = (unsigned)__cvta_generic_to_shared(&sw[s][tld]);

    const float* xp[4];
    #pragma unroll
    for (int bb = 0; bb < 4; ++bb)
        xp[bb] = x + (size_t)((bbase + bb) * IC_) * E_;

    float bo[8];
    #pragma unroll
    for (int oo = 0; oo < 8; ++oo) bo[oo] = __ldg(&bias[oh * 8 + oo]);

    const int tile0  = blockIdx.x;
    const int ntiles = (NTILE - tile0 + gstride - 1) / gstride;
    const int mtot   = ntiles * IC_;

    // ---- stage-issue state ----
    int s_ic = 0;
    const float4* s_w = wbase + tile0 * KT;
    int issued = 0;
    #pragma unroll
    for (int s = 0; s < 3; ++s) {
        cp_async16(swdst[s], s_w + (size_t)s_ic * KTOT);
        cp_commit();
        ++s_ic; ++issued;
    }

    // ---- x-gather state ----
    int k0 = tile0 * KT;
    int k  = k0 + lane;
    int c0 = k;
    int c2 = VOFF + (k0 >> 8) * 257 + (k0 & 255) + lane;

    float xf[4][4];
    #pragma unroll
    for (int bb = 0; bb < 4; ++bb) {
        const float* xb = xp[bb];
        xf[bb][0] = __ldg(xb + c0);
        xf[bb][1] = __ldg(xb + c0 + 256);
        xf[bb][2] = __ldg(xb + c2);
        xf[bb][3] = __ldg(xb + c2 + 1);
    }

    int m = 0;
    for (int t = 0; t < ntiles; ++t) {
        unsigned long long acc[8][4];
        #pragma unroll
        for (int oo = 0; oo < 8; ++oo)
            #pragma unroll
            for (int bb = 0; bb < 4; ++bb) acc[oo][bb] = 0ull;

        #pragma unroll 1
        for (int ic = 0; ic < IC_; ++ic, ++m) {
            const int pend = issued - m - 1;
            if (pend >= 2)      cp_wait<2>();
            else if (pend == 1) cp_wait<1>();
            else                cp_wait<0>();
            bar_named(1 + oh);          // sync only this oh-half (256 threads)

            if (issued < mtot) {
                cp_async16(swdst[issued & (NBUF - 1)], s_w + (size_t)s_ic * KTOT);
                cp_commit();
                if (++s_ic == IC_) { s_ic = 0; s_w += (size_t)gstride * KT; }
                ++issued;
            }

            // pack current x
            unsigned long long xA[4], xB[4];
            #pragma unroll
            for (int bb = 0; bb < 4; ++bb) {
                xA[bb] = pack2(xf[bb][0], xf[bb][1]);
                xB[bb] = pack2(xf[bb][2], xf[bb][3]);
            }

            // prefetch x for the next stage
            if (ic < IC_ - 1) {
                const int off = (ic + 1) * E_;
                #pragma unroll
                for (int bb = 0; bb < 4; ++bb) {
                    const float* xb = xp[bb] + off;
                    xf[bb][0] = __ldg(xb + c0);
                    xf[bb][1] = __ldg(xb + c0 + 256);
                    xf[bb][2] = __ldg(xb + c2);
                    xf[bb][3] = __ldg(xb + c2 + 1);
                }
            } else if (t + 1 < ntiles) {
                const int k0n = k0 + gstride * KT;
                const int c0n = k0n + lane;
                const int c2n = VOFF + (k0n >> 8) * 257 + (k0n & 255) + lane;
                #pragma unroll
                for (int bb = 0; bb < 4; ++bb) {
                    const float* xb = xp[bb];
                    xf[bb][0] = __ldg(xb + c0n);
                    xf[bb][1] = __ldg(xb + c0n + 256);
                    xf[bb][2] = __ldg(xb + c2n);
                    xf[bb][3] = __ldg(xb + c2n + 1);
                }
            }

            // compute: 8 o x 4 b x 2 fma2, o-loop rotated per bg warp
            unsigned sa = (unsigned)__cvta_generic_to_shared(
                              &sw[m & (NBUF - 1)][(oh * 8) * KT + lane]);
            #pragma unroll
            for (int oo = 0; oo < 8; ++oo) {
                const int oop = (oo + bg) & 7;        // stagger across bg warps
                unsigned long long wA, wB;
                asm("ld.shared.v2.u64 {%0, %1}, [%2];"
                    : "=l"(wA), "=l"(wB) : "r"(sa + oop * (KT * 16)));
                #pragma unroll
                for (int bb = 0; bb < 4; ++bb) {
                    fma2(acc[oop][bb], wA, xA[bb]);
                    fma2(acc[oop][bb], wB, xB[bb]);
                }
            }
        }

        // epilogue for this tile
        #pragma unroll
        for (int oo = 0; oo < 8; ++oo) {
            const int o = oh * 8 + oo;
            #pragma unroll
            for (int bb = 0; bb < 4; ++bb) {
                float2 v = unpack2(acc[oo][bb]);
                out[(size_t)((bbase + bb) * OC_ + o) * KTOT + k] = v.x + v.y + bo[oo];
            }
        }

        k0 += gstride * KT;
        k   = k0 + lane;
        c0  = k;
        c2  = VOFF + (k0 >> 8) * 257 + (k0 & 255) + lane;
    }
}

extern "C" void kernel_launch(void* const* d_in, const int* in_sizes, int n_in,
                              void* d_out, int out_size)
{
    const float*  x    = (const float*)d_in[0];
    const float4* w4   = (const float4*)d_in[1];
    const float*  bias = (const float*)d_in[2];
    float*        out  = (float*)d_out;

    dim3 block(32, 16);
    dim3 grid(148);
    edges_kernel<<<grid, block>>>(x, w4, bias, out);
}

// round 10
// speedup vs baseline: 3.1567x; 3.1567x over previous
#include <cuda_runtime.h>
#include <cstdint>

#define B_    32
#define IC_   16
#define OC_   16
#define KTOT  65536      // (M-1)*(N-1)
#define E_    131584     // edges
#define VOFF  65792      // M*(N-1)
#define KT    32         // k per tile
#define NBUF  4          // weight pipeline depth
#define NTILE (KTOT / KT)   // 2048

__device__ __forceinline__ unsigned long long pack2(float lo, float hi) {
    unsigned long long r;
    asm("mov.b64 %0, {%1, %2};" : "=l"(r) : "f"(lo), "f"(hi));
    return r;
}
__device__ __forceinline__ void fma2(unsigned long long &acc,
                                     unsigned long long a, unsigned long long b) {
    asm("fma.rn.f32x2 %0, %1, %2, %0;" : "+l"(acc) : "l"(a), "l"(b));
}
__device__ __forceinline__ float2 unpack2(unsigned long long v) {
    float2 f;
    asm("mov.b64 {%0, %1}, %2;" : "=f"(f.x), "=f"(f.y) : "l"(v));
    return f;
}
__device__ __forceinline__ void cp_async16(unsigned dst, const void* src) {
    asm volatile("cp.async.cg.shared.global [%0], [%1], 16;\n"
                 :: "r"(dst), "l"(src) : "memory");
}
__device__ __forceinline__ void cp_commit() {
    asm volatile("cp.async.commit_group;\n" ::: "memory");
}
template<int N>
__device__ __forceinline__ void cp_wait() {
    asm volatile("cp.async.wait_group %0;\n" :: "n"(N) : "memory");
}
__device__ __forceinline__ void bar_named(int id) {
    asm volatile("bar.sync %0, 256;" :: "r"(id) : "memory");
}

// Persistent CTAs: 148 blocks x 512 threads, each walks ~14 k-tiles.
// Per tile: 32 k-lanes x 16 warps (y = oh*8 + bg), all 32 batches, all 16 o.
// Slab rows 0..7 are written by warps 0..7 and read ONLY by warps 0..7 (oh=0);
// rows 8..15 by warps 8..15 -> two fully independent barrier domains
// (named barriers 1 and 2, 256 threads each). No cross-half smem sharing.
__global__ __launch_bounds__(512, 1)
void edges_kernel(const float* __restrict__ x,
                  const float4* __restrict__ w4,
                  const float* __restrict__ bias,
                  float* __restrict__ out)
{
    __shared__ float4 sw[NBUF][16 * KT];   // [buf][o*32 + klocal]

    const int lane = threadIdx.x;
    const int y    = threadIdx.y;
    const int oh   = y >> 3;
    const int bg   = y & 7;
    const int bbase = bg * 4;
    const int gstride = gridDim.x;

    // cooperative weight copy mapping (per-thread slot; warp y -> slab row y)
    const int tld = y * 32 + lane;
    const float4* wbase = w4 + (size_t)((tld >> 5) * IC_) * KTOT + (tld & 31);
    unsigned swdst[NBUF];
    #pragma unroll
    for (int s = 0; s < NBUF; ++s)
        swdst[s] = (unsigned)__cvta_generic_to_shared(&sw[s][tld]);

    const float* xp[4];
    #pragma unroll
    for (int bb = 0; bb < 4; ++bb)
        xp[bb] = x + (size_t)((bbase + bb) * IC_) * E_;

    float bo[8];
    #pragma unroll
    for (int oo = 0; oo < 8; ++oo) bo[oo] = __ldg(&bias[oh * 8 + oo]);

    const int tile0  = blockIdx.x;
    const int ntiles = (NTILE - tile0 + gstride - 1) / gstride;
    const int mtot   = ntiles * IC_;

    // ---- stage-issue state ----
    int s_ic = 0;
    const float4* s_w = wbase + tile0 * KT;
    int issued = 0;
    #pragma unroll
    for (int s = 0; s < 3; ++s) {
        cp_async16(swdst[s], s_w + (size_t)s_ic * KTOT);
        cp_commit();
        ++s_ic; ++issued;
    }

    // ---- x-gather state ----
    int k0 = tile0 * KT;
    int k  = k0 + lane;
    int c0 = k;
    int c2 = VOFF + (k0 >> 8) * 257 + (k0 & 255) + lane;

    float xf[4][4];
    #pragma unroll
    for (int bb = 0; bb < 4; ++bb) {
        const float* xb = xp[bb];
        xf[bb][0] = __ldg(xb + c0);
        xf[bb][1] = __ldg(xb + c0 + 256);
        xf[bb][2] = __ldg(xb + c2);
        xf[bb][3] = __ldg(xb + c2 + 1);
    }

    int m = 0;
    for (int t = 0; t < ntiles; ++t) {
        unsigned long long acc[8][4];
        #pragma unroll
        for (int oo = 0; oo < 8; ++oo)
            #pragma unroll
            for (int bb = 0; bb < 4; ++bb) acc[oo][bb] = 0ull;

        #pragma unroll 1
        for (int ic = 0; ic < IC_; ++ic, ++m) {
            const int pend = issued - m - 1;
            if (pend >= 2)      cp_wait<2>();
            else if (pend == 1) cp_wait<1>();
            else                cp_wait<0>();
            bar_named(1 + oh);          // sync only this oh-half (256 threads)

            if (issued < mtot) {
                cp_async16(swdst[issued & (NBUF - 1)], s_w + (size_t)s_ic * KTOT);
                cp_commit();
                if (++s_ic == IC_) { s_ic = 0; s_w += (size_t)gstride * KT; }
                ++issued;
            }

            // pack current x
            unsigned long long xA[4], xB[4];
            #pragma unroll
            for (int bb = 0; bb < 4; ++bb) {
                xA[bb] = pack2(xf[bb][0], xf[bb][1]);
                xB[bb] = pack2(xf[bb][2], xf[bb][3]);
            }

            // prefetch x for the next stage
            if (ic < IC_ - 1) {
                const int off = (ic + 1) * E_;
                #pragma unroll
                for (int bb = 0; bb < 4; ++bb) {
                    const float* xb = xp[bb] + off;
                    xf[bb][0] = __ldg(xb + c0);
                    xf[bb][1] = __ldg(xb + c0 + 256);
                    xf[bb][2] = __ldg(xb + c2);
                    xf[bb][3] = __ldg(xb + c2 + 1);
                }
            } else if (t + 1 < ntiles) {
                const int k0n = k0 + gstride * KT;
                const int c0n = k0n + lane;
                const int c2n = VOFF + (k0n >> 8) * 257 + (k0n & 255) + lane;
                #pragma unroll
                for (int bb = 0; bb < 4; ++bb) {
                    const float* xb = xp[bb];
                    xf[bb][0] = __ldg(xb + c0n);
                    xf[bb][1] = __ldg(xb + c0n + 256);
                    xf[bb][2] = __ldg(xb + c2n);
                    xf[bb][3] = __ldg(xb + c2n + 1);
                }
            }

            // compute: 8 o x 4 b x 2 fma2 (all indices compile-time)
            unsigned sa = (unsigned)__cvta_generic_to_shared(
                              &sw[m & (NBUF - 1)][(oh * 8) * KT + lane]);
            #pragma unroll
            for (int oo = 0; oo < 8; ++oo) {
                unsigned long long wA, wB;
                asm("ld.shared.v2.u64 {%0, %1}, [%2];"
                    : "=l"(wA), "=l"(wB) : "r"(sa + oo * (KT * 16)));
                #pragma unroll
                for (int bb = 0; bb < 4; ++bb) {
                    fma2(acc[oo][bb], wA, xA[bb]);
                    fma2(acc[oo][bb], wB, xB[bb]);
                }
            }
        }

        // epilogue for this tile
        #pragma unroll
        for (int oo = 0; oo < 8; ++oo) {
            const int o = oh * 8 + oo;
            #pragma unroll
            for (int bb = 0; bb < 4; ++bb) {
                float2 v = unpack2(acc[oo][bb]);
                out[(size_t)((bbase + bb) * OC_ + o) * KTOT + k] = v.x + v.y + bo[oo];
            }
        }

        k0 += gstride * KT;
        k   = k0 + lane;
        c0  = k;
        c2  = VOFF + (k0 >> 8) * 257 + (k0 & 255) + lane;
    }
}

extern "C" void kernel_launch(void* const* d_in, const int* in_sizes, int n_in,
                              void* d_out, int out_size)
{
    const float*  x    = (const float*)d_in[0];
    const float4* w4   = (const float4*)d_in[1];
    const float*  bias = (const float*)d_in[2];
    float*        out  = (float*)d_out;

    dim3 block(32, 16);
    dim3 grid(148);
    edges_kernel<<<grid, block>>>(x, w4, bias, out);
}